// round 15
// baseline (speedup 1.0000x reference)
#include <cuda_runtime.h>
#include <cuda_bf16.h>
#include <cstdint>

#define BATCH     2048
#define NCLASSES  50257
#define KPOS      20
#define TPB       256

#define NSTAGE    3
#define CHUNK_B   8192
#define CHUNK_F   2048          // floats per chunk
#define CHUNK_F4  512           // float4 per chunk

// Scratch (allocation-free requirement -> __device__ global).
__device__ __align__(16) float g_row_loss[BATCH];

// ---------- PTX helpers ----------
__device__ __forceinline__ uint32_t smem_u32(const void* p) {
    return (uint32_t)__cvta_generic_to_shared(p);
}
__device__ __forceinline__ void mbar_init(uint32_t a, uint32_t cnt) {
    asm volatile("mbarrier.init.shared.b64 [%0], %1;" :: "r"(a), "r"(cnt) : "memory");
}
__device__ __forceinline__ void mbar_expect_tx(uint32_t a, uint32_t bytes) {
    asm volatile("mbarrier.arrive.expect_tx.shared.b64 _, [%0], %1;"
                 :: "r"(a), "r"(bytes) : "memory");
}
__device__ __forceinline__ void bulk_g2s(uint32_t dst, const void* src,
                                         uint32_t bytes, uint32_t mbar) {
    asm volatile("cp.async.bulk.shared::cta.global.mbarrier::complete_tx::bytes "
                 "[%0], [%1], %2, [%3];"
                 :: "r"(dst), "l"(src), "r"(bytes), "r"(mbar) : "memory");
}
__device__ __forceinline__ void mbar_wait(uint32_t a, uint32_t phase) {
    asm volatile(
        "{\n\t"
        ".reg .pred P;\n\t"
        "W_%=:\n\t"
        "mbarrier.try_wait.parity.acquire.cta.shared::cta.b64 P, [%0], %1, 0x989680;\n\t"
        "@P bra D_%=;\n\t"
        "bra W_%=;\n\t"
        "D_%=:\n\t"
        "}"
        :: "r"(a), "r"(phase) : "memory");
}
// ---------------------------------

__device__ __forceinline__ float softplus_f(float x) {
    return fmaxf(x, 0.0f) + __logf(1.0f + __expf(-fabsf(x)));
}

// Accumulate max(x,0) linearly; fold log terms into products (factor in (1,2]).
#define PROC4(v)                                                        \
    do {                                                                \
        lin += fmaxf((v).x, 0.0f) + fmaxf((v).y, 0.0f)                  \
             + fmaxf((v).z, 0.0f) + fmaxf((v).w, 0.0f);                 \
        p0 *= (1.0f + __expf(-fabsf((v).x)))                            \
            * (1.0f + __expf(-fabsf((v).y)));                           \
        p1 *= (1.0f + __expf(-fabsf((v).z)))                            \
            * (1.0f + __expf(-fabsf((v).w)));                           \
    } while (0)

__global__ __launch_bounds__(TPB)
void mlsm_row_kernel(const float* __restrict__ inp, const int* __restrict__ tgt) {
    const int row = blockIdx.x;
    const int tid = threadIdx.x;

    __shared__ __align__(16) float s_buf[NSTAGE][CHUNK_F];
    __shared__ __align__(8)  unsigned long long s_mbar[NSTAGE];
    __shared__ int   s_t[KPOS];
    __shared__ float s_warp[TPB / 32];
    __shared__ float s_total;

    const long long rowstart = (long long)row * NCLASSES;
    const long long rowend   = rowstart + NCLASSES;
    // 16B-aligned enclosing span (element units). Over-read stays in-bounds:
    // preceding elements belong to the previous row; the last row's end is
    // exactly 16B-aligned (BATCH*NCLASSES divisible by 4).
    const long long g0 = rowstart & ~3LL;
    const long long g1 = (rowend + 3LL) & ~3LL;
    const int nelem = (int)(g1 - g0);                 // multiple of 4
    const int nch   = (nelem + CHUNK_F - 1) / CHUNK_F;

    if (tid < KPOS) s_t[tid] = tgt[row * KPOS + tid];

    uint32_t mb[NSTAGE];
    #pragma unroll
    for (int s = 0; s < NSTAGE; ++s) mb[s] = smem_u32(&s_mbar[s]);

    if (tid == 0) {
        #pragma unroll
        for (int s = 0; s < NSTAGE; ++s) mbar_init(mb[s], 1);
    }
    __syncthreads();

    // Prologue: keep NSTAGE bulk copies in flight from the start.
    if (tid == 0) {
        for (int c = 0; c < NSTAGE && c < nch; ++c) {
            const int bytes = min(CHUNK_B, nelem * 4 - c * CHUNK_B);
            mbar_expect_tx(mb[c], (uint32_t)bytes);
            bulk_g2s(smem_u32(s_buf[c]), inp + g0 + (long long)c * CHUNK_F,
                     (uint32_t)bytes, mb[c]);
        }
    }

    float acc = 0.0f;
    for (int c = 0; c < nch; ++c) {
        const int buf   = c % NSTAGE;
        const int phase = (c / NSTAGE) & 1;
        mbar_wait(mb[buf], (uint32_t)phase);

        const long long ebase = g0 + (long long)c * CHUNK_F;
        const float4* __restrict__ sb = (const float4*)s_buf[buf];
        float lin = 0.0f, p0 = 1.0f, p1 = 1.0f;

        if (ebase >= rowstart && ebase + CHUNK_F <= rowend) {
            // Full interior chunk: 2 float4 per thread, unconditional.
            float4 v0 = sb[tid];
            float4 v1 = sb[tid + TPB];
            PROC4(v0); PROC4(v1);
        } else {
            // Boundary chunk: per-element row-range guard.
            const int f4cnt = min(CHUNK_F4, (nelem - c * CHUNK_F) >> 2);
            for (int k = tid; k < f4cnt; k += TPB) {
                float4 v = sb[k];
                const long long eg = ebase + 4LL * k;
                float xs[4] = {v.x, v.y, v.z, v.w};
                #pragma unroll
                for (int j = 0; j < 4; ++j) {
                    const long long e = eg + j;
                    if (e >= rowstart && e < rowend) {
                        lin += fmaxf(xs[j], 0.0f);
                        p0  *= (1.0f + __expf(-fabsf(xs[j])));
                    }
                }
            }
        }
        acc += lin + __logf(p0 * p1);   // <=8 factors -> prod <= 2^8, fp32-safe

        __syncthreads();                 // all threads done reading this buffer
        const int cn = c + NSTAGE;
        if (tid == 0 && cn < nch) {
            const int bytes = min(CHUNK_B, nelem * 4 - cn * CHUNK_B);
            mbar_expect_tx(mb[buf], (uint32_t)bytes);
            bulk_g2s(smem_u32(s_buf[buf]), inp + g0 + (long long)cn * CHUNK_F,
                     (uint32_t)bytes, mb[buf]);
        }
    }

    // Block reduce -> s_total (sum of softplus over the row).
    const int lane = tid & 31;
    const int wid  = tid >> 5;
    #pragma unroll
    for (int o = 16; o > 0; o >>= 1)
        acc += __shfl_down_sync(0xFFFFFFFFu, acc, o);
    if (lane == 0) s_warp[wid] = acc;
    __syncthreads();
    if (wid == 0) {
        float v = (lane < TPB / 32) ? s_warp[lane] : 0.0f;
        #pragma unroll
        for (int o = 16; o > 0; o >>= 1)
            v += __shfl_down_sync(0xFFFFFFFFu, v, o);
        if (lane == 0) s_total = v;
    }
    __syncthreads();

    // Warp 0: K=20 label handling -> row loss, then PDL signal.
    if (wid == 0) {
        const float* __restrict__ rp = inp + rowstart;
        float pos = 0.0f, corr = 0.0f;
        int   nfirst = 0;
        if (lane < KPOS) {
            const int t = s_t[lane];
            const float x = __ldg(rp + t);
            pos = -softplus_f(-x);                 // log_sigmoid, per occurrence
            bool first = true;
            #pragma unroll
            for (int j = 0; j < KPOS; ++j)
                if (j < lane && s_t[j] == t) first = false;
            if (first) { corr = softplus_f(x); nfirst = 1; }  // dedup'd
        }
        #pragma unroll
        for (int o = 16; o > 0; o >>= 1) {
            pos    += __shfl_down_sync(0xFFFFFFFFu, pos, o);
            corr   += __shfl_down_sync(0xFFFFFFFFu, corr, o);
            nfirst += __shfl_down_sync(0xFFFFFFFFu, nfirst, o);
        }
        if (lane == 0) {
            const float neg_mean = (corr - s_total) / (float)(NCLASSES - nfirst);
            g_row_loss[row] = pos / (float)KPOS + neg_mean;
            asm volatile("griddepcontrol.launch_dependents;" ::: "memory");
        }
    }
}

__global__ __launch_bounds__(256)
void mlsm_reduce_kernel(float* __restrict__ out) {
    asm volatile("griddepcontrol.wait;" ::: "memory");

    const int tid  = threadIdx.x;
    const int lane = tid & 31;
    const int wid  = tid >> 5;
    __shared__ float s_warp[8];

    const float4* __restrict__ v = (const float4*)g_row_loss;
    float4 x = v[tid];
    float4 y = v[tid + 256];
    float a = ((x.x + x.y) + (x.z + x.w)) + ((y.x + y.y) + (y.z + y.w));

    #pragma unroll
    for (int o = 16; o > 0; o >>= 1)
        a += __shfl_down_sync(0xFFFFFFFFu, a, o);
    if (lane == 0) s_warp[wid] = a;
    __syncthreads();
    if (wid == 0) {
        float t = (lane < 8) ? s_warp[lane] : 0.0f;
        #pragma unroll
        for (int o = 4; o > 0; o >>= 1)
            t += __shfl_down_sync(0xFFFFFFFFu, t, o);
        if (lane == 0)
            out[0] = -t / (float)BATCH;
    }
}

extern "C" void kernel_launch(void* const* d_in, const int* in_sizes, int n_in,
                              void* d_out, int out_size) {
    const float* inp = (const float*)d_in[0];
    const int*   tgt = (const int*)d_in[1];
    if (n_in >= 2 && in_sizes[0] == BATCH * KPOS && in_sizes[1] == BATCH * NCLASSES) {
        inp = (const float*)d_in[1];
        tgt = (const int*)d_in[0];
    }

    mlsm_row_kernel<<<BATCH, TPB>>>(inp, tgt);

    cudaLaunchConfig_t cfg = {};
    cfg.gridDim  = dim3(1, 1, 1);
    cfg.blockDim = dim3(256, 1, 1);
    cfg.dynamicSmemBytes = 0;
    cfg.stream = 0;
    cudaLaunchAttribute attr[1];
    attr[0].id = cudaLaunchAttributeProgrammaticStreamSerialization;
    attr[0].val.programmaticStreamSerializationAllowed = 1;
    cfg.attrs = attr;
    cfg.numAttrs = 1;
    cudaLaunchKernelEx(&cfg, mlsm_reduce_kernel, (float*)d_out);
}

// round 16
// speedup vs baseline: 1.0481x; 1.0481x over previous
#include <cuda_runtime.h>
#include <cuda_bf16.h>
#include <cstdint>

#define BATCH     2048
#define NCLASSES  50257
#define KPOS      20
#define TPB       256

// Scratch (allocation-free requirement -> __device__ globals; zero-initialized).
__device__ __align__(16) float g_row_loss[BATCH];
__device__ unsigned int g_flag[BATCH];   // 1 = row loss published (release)

__device__ __forceinline__ void st_release_u32(unsigned int* p, unsigned int v) {
    asm volatile("st.release.gpu.global.u32 [%0], %1;" :: "l"(p), "r"(v) : "memory");
}
__device__ __forceinline__ unsigned int ld_acquire_u32(const unsigned int* p) {
    unsigned int v;
    asm volatile("ld.acquire.gpu.global.u32 %0, [%1];" : "=r"(v) : "l"(p) : "memory");
    return v;
}

__device__ __forceinline__ float softplus_f(float x) {
    // log(1+exp(x)) = max(x,0) + log(1+exp(-|x|)); exp arg <= 0 -> value in (0,1]
    return fmaxf(x, 0.0f) + __logf(1.0f + __expf(-fabsf(x)));
}

// Accumulate max(x,0) linearly; fold log terms into products (factor in (1,2]).
// One __logf per <=16 factors (prod <= 2^16, fp32-safe).
#define PROC4(v)                                                        \
    do {                                                                \
        lin += fmaxf((v).x, 0.0f) + fmaxf((v).y, 0.0f)                  \
             + fmaxf((v).z, 0.0f) + fmaxf((v).w, 0.0f);                 \
        p0 *= (1.0f + __expf(-fabsf((v).x)))                            \
            * (1.0f + __expf(-fabsf((v).y)));                           \
        p1 *= (1.0f + __expf(-fabsf((v).z)))                            \
            * (1.0f + __expf(-fabsf((v).w)));                           \
    } while (0)

__global__ __launch_bounds__(TPB)
void mlsm_row_kernel(const float* __restrict__ inp, const int* __restrict__ tgt) {
    const int row = blockIdx.x;
    const int tid = threadIdx.x;
    const float* __restrict__ rp = inp + (size_t)row * NCLASSES;

    // PDL: signal immediately. The dependent reduce kernel launches once every
    // row CTA has *started*; it synchronizes on the per-row flag protocol
    // below, not on griddepcontrol.wait, so this early signal is safe.
    if (tid == 0)
        asm volatile("griddepcontrol.launch_dependents;" ::: "memory");

    __shared__ int   s_t[KPOS];
    __shared__ float s_warp[TPB / 32];
    __shared__ float s_total;

    if (tid < KPOS) s_t[tid] = tgt[row * KPOS + tid];

    // Row base only 4B-aligned (NCLASSES odd): scalar prologue to 16B alignment.
    const int mis = (int)(((size_t)row * NCLASSES) & 3);
    const int pro = (4 - mis) & 3;

    float acc = 0.0f;
    if (tid < pro) acc += softplus_f(rp[tid]);

    const float4* __restrict__ vp = (const float4*)(rp + pro);
    const int nv = (NCLASSES - pro) >> 2;

    // R4/R14-proven hot loop: 4 front-batched LDG.128 (MLP=4), default
    // caching, 16 elements per __logf. No tail code in the stream.
    int i = tid;
    for (; i + 3 * TPB < nv; i += 4 * TPB) {
        float4 a = vp[i];
        float4 b = vp[i + TPB];
        float4 c = vp[i + 2 * TPB];
        float4 d = vp[i + 3 * TPB];
        float lin = 0.0f, p0 = 1.0f, p1 = 1.0f;
        PROC4(a); PROC4(b); PROC4(c); PROC4(d);
        acc += lin + __logf(p0 * p1);
    }
    for (; i < nv; i += TPB) {
        float4 a = vp[i];
        float lin = 0.0f, p0 = 1.0f, p1 = 1.0f;
        PROC4(a);
        acc += lin + __logf(p0 * p1);
    }
    const int base = pro + (nv << 2);
    for (int j = base + tid; j < NCLASSES; j += TPB)
        acc += softplus_f(rp[j]);

    // Block reduce -> s_total (sum of softplus over the row).
    const int lane = tid & 31;
    const int wid  = tid >> 5;
    #pragma unroll
    for (int o = 16; o > 0; o >>= 1)
        acc += __shfl_down_sync(0xFFFFFFFFu, acc, o);
    if (lane == 0) s_warp[wid] = acc;
    __syncthreads();
    if (wid == 0) {
        float v = (lane < TPB / 32) ? s_warp[lane] : 0.0f;
        #pragma unroll
        for (int o = 16; o > 0; o >>= 1)
            v += __shfl_down_sync(0xFFFFFFFFu, v, o);
        if (lane == 0) s_total = v;
    }
    __syncthreads();

    // Warp 0: K=20 label handling -> row loss, published via release flag.
    if (wid == 0) {
        float pos = 0.0f, corr = 0.0f;
        int   nfirst = 0;
        if (lane < KPOS) {
            const int t = s_t[lane];
            const float x = __ldg(rp + t);
            pos = -softplus_f(-x);                 // log_sigmoid, per occurrence
            bool first = true;
            #pragma unroll
            for (int j = 0; j < KPOS; ++j)
                if (j < lane && s_t[j] == t) first = false;
            if (first) { corr = softplus_f(x); nfirst = 1; }  // dedup'd
        }
        #pragma unroll
        for (int o = 16; o > 0; o >>= 1) {
            pos    += __shfl_down_sync(0xFFFFFFFFu, pos, o);
            corr   += __shfl_down_sync(0xFFFFFFFFu, corr, o);
            nfirst += __shfl_down_sync(0xFFFFFFFFu, nfirst, o);
        }
        if (lane == 0) {
            const float neg_mean = (corr - s_total) / (float)(NCLASSES - nfirst);
            g_row_loss[row] = pos / (float)KPOS + neg_mean;
            st_release_u32(&g_flag[row], 1u);      // publish (release)
        }
    }
}

__global__ __launch_bounds__(256)
void mlsm_reduce_kernel(float* __restrict__ out) {
    // Runs concurrently with the tail of the row kernel (early PDL signal).
    // Consumes rows as they are published; fixed per-thread row set and fixed
    // reduction tree -> bitwise deterministic.
    const int tid  = threadIdx.x;
    const int lane = tid & 31;
    const int wid  = tid >> 5;
    __shared__ float s_warp[8];

    float a = 0.0f;
    #pragma unroll
    for (int k = 0; k < BATCH / 256; ++k) {
        const int r = tid + k * 256;
        while (ld_acquire_u32(&g_flag[r]) == 0u) { }   // spin until published
        a += __ldcg(&g_row_loss[r]);
        g_flag[r] = 0u;                 // reset for next graph replay
    }

    #pragma unroll
    for (int o = 16; o > 0; o >>= 1)
        a += __shfl_down_sync(0xFFFFFFFFu, a, o);
    if (lane == 0) s_warp[wid] = a;
    __syncthreads();
    if (wid == 0) {
        float t = (lane < 8) ? s_warp[lane] : 0.0f;
        #pragma unroll
        for (int o = 4; o > 0; o >>= 1)
            t += __shfl_down_sync(0xFFFFFFFFu, t, o);
        if (lane == 0)
            out[0] = -t / (float)BATCH;
    }
}

extern "C" void kernel_launch(void* const* d_in, const int* in_sizes, int n_in,
                              void* d_out, int out_size) {
    const float* inp = (const float*)d_in[0];
    const int*   tgt = (const int*)d_in[1];
    if (n_in >= 2 && in_sizes[0] == BATCH * KPOS && in_sizes[1] == BATCH * NCLASSES) {
        inp = (const float*)d_in[1];
        tgt = (const int*)d_in[0];
    }

    mlsm_row_kernel<<<BATCH, TPB>>>(inp, tgt);

    // PDL dependent launch: resident and polling while the row kernel runs.
    cudaLaunchConfig_t cfg = {};
    cfg.gridDim  = dim3(1, 1, 1);
    cfg.blockDim = dim3(256, 1, 1);
    cfg.dynamicSmemBytes = 0;
    cfg.stream = 0;
    cudaLaunchAttribute attr[1];
    attr[0].id = cudaLaunchAttributeProgrammaticStreamSerialization;
    attr[0].val.programmaticStreamSerializationAllowed = 1;
    cfg.attrs = attr;
    cfg.numAttrs = 1;
    cudaLaunchKernelEx(&cfg, mlsm_reduce_kernel, (float*)d_out);
}

// round 17
// speedup vs baseline: 1.0782x; 1.0287x over previous
#include <cuda_runtime.h>
#include <cuda_bf16.h>
#include <cstdint>

#define BATCH     2048
#define NCLASSES  50257
#define KPOS      20
#define TPB       256

// Scratch (allocation-free requirement -> __device__ globals; zero-initialized).
__device__ __align__(16) float g_row_loss[BATCH];
__device__ unsigned int g_done = 0;

// No-return reduction with release semantics: publishes this thread's prior
// stores (the row loss) without a full MEMBAR flush and without a return trip.
__device__ __forceinline__ void red_release_add(unsigned int* p, unsigned int v) {
    asm volatile("red.release.gpu.global.add.u32 [%0], %1;" :: "l"(p), "r"(v) : "memory");
}
__device__ __forceinline__ unsigned int ld_acquire_u32(const unsigned int* p) {
    unsigned int v;
    asm volatile("ld.acquire.gpu.global.u32 %0, [%1];" : "=r"(v) : "l"(p) : "memory");
    return v;
}

__device__ __forceinline__ float softplus_f(float x) {
    // log(1+exp(x)) = max(x,0) + log(1+exp(-|x|)); exp arg <= 0 -> value in (0,1]
    return fmaxf(x, 0.0f) + __logf(1.0f + __expf(-fabsf(x)));
}

// Accumulate max(x,0) linearly; fold log terms into products (factor in (1,2]).
// One __logf per <=16 factors (prod <= 2^16, fp32-safe).
#define PROC4(v)                                                        \
    do {                                                                \
        lin += fmaxf((v).x, 0.0f) + fmaxf((v).y, 0.0f)                  \
             + fmaxf((v).z, 0.0f) + fmaxf((v).w, 0.0f);                 \
        p0 *= (1.0f + __expf(-fabsf((v).x)))                            \
            * (1.0f + __expf(-fabsf((v).y)));                           \
        p1 *= (1.0f + __expf(-fabsf((v).z)))                            \
            * (1.0f + __expf(-fabsf((v).w)));                           \
    } while (0)

__global__ __launch_bounds__(TPB)
void mlsm_row_kernel(const float* __restrict__ inp, const int* __restrict__ tgt) {
    const int row = blockIdx.x;
    const int tid = threadIdx.x;
    const float* __restrict__ rp = inp + (size_t)row * NCLASSES;

    // PDL: signal immediately so the dependent reducer goes resident mid-run.
    // Correctness does NOT rely on griddepcontrol.wait visibility; the reducer
    // synchronizes on the release/acquire counter protocol below.
    if (tid == 0)
        asm volatile("griddepcontrol.launch_dependents;" ::: "memory");

    __shared__ int   s_t[KPOS];
    __shared__ float s_warp[TPB / 32];
    __shared__ float s_total;

    if (tid < KPOS) s_t[tid] = tgt[row * KPOS + tid];

    // Row base only 4B-aligned (NCLASSES odd): scalar prologue to 16B alignment.
    const int mis = (int)(((size_t)row * NCLASSES) & 3);
    const int pro = (4 - mis) & 3;

    float acc = 0.0f;
    if (tid < pro) acc += softplus_f(rp[tid]);

    const float4* __restrict__ vp = (const float4*)(rp + pro);
    const int nv = (NCLASSES - pro) >> 2;

    // R4/R14-proven hot loop: 4 front-batched LDG.128 (MLP=4), default
    // caching, 16 elements per __logf. No tail code in the stream.
    int i = tid;
    for (; i + 3 * TPB < nv; i += 4 * TPB) {
        float4 a = vp[i];
        float4 b = vp[i + TPB];
        float4 c = vp[i + 2 * TPB];
        float4 d = vp[i + 3 * TPB];
        float lin = 0.0f, p0 = 1.0f, p1 = 1.0f;
        PROC4(a); PROC4(b); PROC4(c); PROC4(d);
        acc += lin + __logf(p0 * p1);
    }
    for (; i < nv; i += TPB) {
        float4 a = vp[i];
        float lin = 0.0f, p0 = 1.0f, p1 = 1.0f;
        PROC4(a);
        acc += lin + __logf(p0 * p1);
    }
    const int base = pro + (nv << 2);
    for (int j = base + tid; j < NCLASSES; j += TPB)
        acc += softplus_f(rp[j]);

    // Block reduce -> s_total (sum of softplus over the row).
    const int lane = tid & 31;
    const int wid  = tid >> 5;
    #pragma unroll
    for (int o = 16; o > 0; o >>= 1)
        acc += __shfl_down_sync(0xFFFFFFFFu, acc, o);
    if (lane == 0) s_warp[wid] = acc;
    __syncthreads();
    if (wid == 0) {
        float v = (lane < TPB / 32) ? s_warp[lane] : 0.0f;
        #pragma unroll
        for (int o = 16; o > 0; o >>= 1)
            v += __shfl_down_sync(0xFFFFFFFFu, v, o);
        if (lane == 0) s_total = v;
    }
    __syncthreads();

    // Warp 0: K=20 label handling -> row loss, published via release REDG.
    if (wid == 0) {
        float pos = 0.0f, corr = 0.0f;
        int   nfirst = 0;
        if (lane < KPOS) {
            const int t = s_t[lane];
            const float x = __ldg(rp + t);
            pos = -softplus_f(-x);                 // log_sigmoid, per occurrence
            bool first = true;
            #pragma unroll
            for (int j = 0; j < KPOS; ++j)
                if (j < lane && s_t[j] == t) first = false;
            if (first) { corr = softplus_f(x); nfirst = 1; }  // dedup'd
        }
        #pragma unroll
        for (int o = 16; o > 0; o >>= 1) {
            pos    += __shfl_down_sync(0xFFFFFFFFu, pos, o);
            corr   += __shfl_down_sync(0xFFFFFFFFu, corr, o);
            nfirst += __shfl_down_sync(0xFFFFFFFFu, nfirst, o);
        }
        if (lane == 0) {
            const float neg_mean = (corr - s_total) / (float)(NCLASSES - nfirst);
            g_row_loss[row] = pos / (float)KPOS + neg_mean;
            red_release_add(&g_done, 1u);          // publish: no-return, release
        }
    }
}

__global__ __launch_bounds__(256)
void mlsm_reduce_kernel(float* __restrict__ out) {
    const int tid  = threadIdx.x;
    const int lane = tid & 31;
    const int wid  = tid >> 5;
    __shared__ float s_warp[8];

    // Only thread 0 polls, with sleep backoff: ~one 4B load per 128ns —
    // negligible interference with the row kernel's stream (R16's failure).
    if (tid == 0) {
        while (ld_acquire_u32(&g_done) != (unsigned int)BATCH)
            __nanosleep(128);
    }
    __syncthreads();   // acquire by tid0 + barrier -> row losses visible to all

    // 2048 floats, fixed per-thread set and fixed tree -> deterministic.
    const float4* __restrict__ v = (const float4*)g_row_loss;
    float4 x = v[tid];
    float4 y = v[tid + 256];
    float a = ((x.x + x.y) + (x.z + x.w)) + ((y.x + y.y) + (y.z + y.w));

    #pragma unroll
    for (int o = 16; o > 0; o >>= 1)
        a += __shfl_down_sync(0xFFFFFFFFu, a, o);
    if (lane == 0) s_warp[wid] = a;
    __syncthreads();
    if (wid == 0) {
        float t = (lane < 8) ? s_warp[lane] : 0.0f;
        #pragma unroll
        for (int o = 4; o > 0; o >>= 1)
            t += __shfl_down_sync(0xFFFFFFFFu, t, o);
        if (lane == 0) {
            out[0] = -t / (float)BATCH;
            g_done = 0u;                           // reset for next replay
        }
    }
}

extern "C" void kernel_launch(void* const* d_in, const int* in_sizes, int n_in,
                              void* d_out, int out_size) {
    const float* inp = (const float*)d_in[0];
    const int*   tgt = (const int*)d_in[1];
    if (n_in >= 2 && in_sizes[0] == BATCH * KPOS && in_sizes[1] == BATCH * NCLASSES) {
        inp = (const float*)d_in[1];
        tgt = (const int*)d_in[0];
    }

    mlsm_row_kernel<<<BATCH, TPB>>>(inp, tgt);

    // PDL dependent launch: resident (sleep-polling) while the row kernel runs.
    cudaLaunchConfig_t cfg = {};
    cfg.gridDim  = dim3(1, 1, 1);
    cfg.blockDim = dim3(256, 1, 1);
    cfg.dynamicSmemBytes = 0;
    cfg.stream = 0;
    cudaLaunchAttribute attr[1];
    attr[0].id = cudaLaunchAttributeProgrammaticStreamSerialization;
    attr[0].val.programmaticStreamSerializationAllowed = 1;
    cfg.attrs = attr;
    cfg.numAttrs = 1;
    cudaLaunchKernelEx(&cfg, mlsm_reduce_kernel, (float*)d_out);
}